// round 4
// baseline (speedup 1.0000x reference)
#include <cuda_runtime.h>

// Problem constants
#define H_   768
#define NCT_ 4096
#define NL_  8921
#define NN_  4

// Self-restoring accumulator scratch (zero-init; finalize re-zeroes each call)
__device__ float g_G[8 * H_];          // column sums of reshaped label_weights per l-group
__device__ float g_E[8 * H_];          // per-chunk column sums of encoding
__device__ unsigned int g_count = 0;   // last-arrival counter (reset by finalize)

static constexpr int TILE_ROWS = 32;
static constexpr int NB_LW = (NL_ + TILE_ROWS - 1) / TILE_ROWS;  // 279
static constexpr int NB_EN = NCT_ / TILE_ROWS;                   // 128
static constexpr int NB = NB_LW + NB_EN;                         // 407

__global__ __launch_bounds__(192) void fused_kernel(
    const float4* __restrict__ lw4, const float4* __restrict__ enc4,
    const float* __restrict__ lw, const void* __restrict__ ids_raw,
    float* __restrict__ out)
{
    const int t = threadIdx.x;
    const int b = blockIdx.x;

    // ---------------- Phase 1: streaming segment column-sums ----------------
    const float4* src;
    float* dst;
    int row0, rend, seg0, seg1, split;

    if (b < NB_LW) {
        row0 = b * TILE_ROWS;
        rend = min(row0 + TILE_ROWS, NL_);
        src = lw4; dst = g_G;
        const int LB[7] = {1113, 2229, 3344, 4459, 5574, 6689, 7804};
        seg0 = 0; seg1 = 0;
        #pragma unroll
        for (int i = 0; i < 7; i++) {
            seg0 += (row0 >= LB[i]);
            seg1 += (rend - 1 >= LB[i]);
        }
        split = (seg1 == seg0) ? rend : LB[seg0];
    } else {
        int b2 = b - NB_LW;
        row0 = b2 * TILE_ROWS;
        rend = row0 + TILE_ROWS;
        src = enc4; dst = g_E;
        seg0 = row0 >> 9;   // 512 rows per chunk; tiles aligned -> no split
        seg1 = seg0;
        split = rend;
    }

    float ax = 0.f, ay = 0.f, az = 0.f, aw = 0.f;
    int r = row0;
    #pragma unroll 4
    for (; r < split; ++r) {
        float4 v = __ldg(&src[r * (H_ / 4) + t]);
        ax += v.x; ay += v.y; az += v.z; aw += v.w;
    }
    {
        float* p = dst + seg0 * H_ + t * 4;
        atomicAdd(p + 0, ax); atomicAdd(p + 1, ay);
        atomicAdd(p + 2, az); atomicAdd(p + 3, aw);
    }
    if (r < rend) {
        ax = ay = az = aw = 0.f;
        #pragma unroll 4
        for (; r < rend; ++r) {
            float4 v = __ldg(&src[r * (H_ / 4) + t]);
            ax += v.x; ay += v.y; az += v.z; aw += v.w;
        }
        float* p = dst + seg1 * H_ + t * 4;
        atomicAdd(p + 0, ax); atomicAdd(p + 1, ay);
        atomicAdd(p + 2, az); atomicAdd(p + 3, aw);
    }

    // ---------------- Last-arrival gate ----------------
    __threadfence();
    __shared__ bool is_last;
    if (t == 0)
        is_last = (atomicAdd(&g_count, 1u) == (unsigned)(gridDim.x - 1));
    __syncthreads();
    if (!is_last) return;
    __threadfence();  // acquire accumulators published by other blocks

    // ---------------- Phase 2: finalize (one block, 192 threads) ----------------
    // note_end_chunk_ids: detect int64 vs int32 (values small nonneg, sorted)
    const int* i32 = (const int*)ids_raw;
    int id[4];
    if (i32[1] == 0 && i32[3] == 0) {            // int64 layout
        const long long* i64 = (const long long*)ids_raw;
        #pragma unroll
        for (int i = 0; i < 4; i++) id[i] = (int)i64[i];
    } else {
        #pragma unroll
        for (int i = 0; i < 4; i++) id[i] = i32[i];
    }

    // w(n,c): softmax over notes of the (0 / -1e9) mask, chunk-piecewise
    float wn[NN_][8];
    #pragma unroll
    for (int c = 0; c < 8; c++) {
        int k = (id[0] < c) + (id[1] < c) + (id[2] < c) + (id[3] < c);
        #pragma unroll
        for (int n = 0; n < NN_; n++)
            wn[n][c] = (k == 0) ? 0.25f : ((id[n] < c) ? (1.0f / (float)k) : 0.0f);
    }

    const int SL[15] = {1113,1114,1115, 2229,2230, 3344,3345, 4459,4460,
                        5574,5575, 6689,6690, 7804,7805};
    const int SC[15] = {0,0,0, 1,1, 2,2, 3,3, 4,4, 5,5, 6,6};
    const int SM[15] = {8,8,1, 8,2, 8,3, 8,4, 8,5, 8,6, 8,7};

    #pragma unroll
    for (int hh = 0; hh < H_ / 192; hh++) {
        const int h = t + hh * 192;

        // Prefix sums of encoding chunk sums
        float Pm[9];
        Pm[0] = 0.0f;
        #pragma unroll
        for (int m = 1; m <= 8; m++) Pm[m] = Pm[m - 1] + g_E[(m - 1) * H_ + h];
        const float Ptot = Pm[8];

        float Gc[8];
        #pragma unroll
        for (int c = 0; c < 8; c++) Gc[c] = g_G[c * H_ + h];

        float LWv[15];
        #pragma unroll
        for (int j = 0; j < 15; j++) LWv[j] = __ldg(&lw[SL[j] * H_ + h]);

        #pragma unroll
        for (int n = 0; n < NN_; n++) {
            float gacc = 0.0f;
            #pragma unroll
            for (int c = 0; c < 8; c++) gacc += wn[n][c] * Gc[c];
            float score = Ptot * gacc;
            #pragma unroll
            for (int j = 0; j < 15; j++) {
                float d = wn[n][SC[j]] - wn[n][SC[j] + 1];
                score += d * LWv[j] * Pm[SM[j]];
            }
            out[n * H_ + h] = 1.0f / (1.0f + expf(-score));
        }
    }

    // ---------------- Restore state for the next graph replay ----------------
    __syncthreads();
    for (int i = t; i < 8 * H_; i += 192) { g_G[i] = 0.0f; g_E[i] = 0.0f; }
    if (t == 0) g_count = 0;
}

extern "C" void kernel_launch(void* const* d_in, const int* in_sizes, int n_in,
                              void* d_out, int out_size) {
    const float* encoding      = (const float*)d_in[0];
    // d_in[1] = label_queries: provably unused (softmax over notes cancels it)
    const float* label_weights = (const float*)d_in[2];
    const void*  ids           = d_in[3];
    float* out = (float*)d_out;

    fused_kernel<<<NB, 192>>>((const float4*)label_weights,
                              (const float4*)encoding,
                              label_weights, ids, out);
}

// round 5
// speedup vs baseline: 1.0826x; 1.0826x over previous
#include <cuda_runtime.h>

// Problem constants
#define H_   768
#define NCT_ 4096
#define NL_  8921
#define NN_  4

// Self-restoring accumulator scratch (zero-init; finalize re-zeroes each call)
__device__ float g_G[8 * H_];          // column sums of reshaped label_weights per l-group
__device__ float g_E[8 * H_];          // per-chunk column sums of encoding
__device__ unsigned int g_count = 0;   // last-arrival counter (reset by finalize)

static constexpr int TILE_ROWS = 32;
static constexpr int NB_LW = (NL_ + TILE_ROWS - 1) / TILE_ROWS;  // 279
static constexpr int NB_EN = NCT_ / TILE_ROWS;                   // 128
static constexpr int NB = NB_LW + NB_EN;                         // 407

__global__ __launch_bounds__(192, 8) void fused_kernel(
    const float4* __restrict__ lw4, const float4* __restrict__ enc4,
    const float* __restrict__ lw, const void* __restrict__ ids_raw,
    float* __restrict__ out)
{
    const int t = threadIdx.x;
    const int b = blockIdx.x;

    // ---------------- Phase 1: streaming segment column-sums ----------------
    const float4* src;
    float* dst;
    int row0, rend, seg0, seg1, split;

    if (b < NB_LW) {
        row0 = b * TILE_ROWS;
        rend = min(row0 + TILE_ROWS, NL_);
        src = lw4; dst = g_G;
        const int LB[7] = {1113, 2229, 3344, 4459, 5574, 6689, 7804};
        seg0 = 0; seg1 = 0;
        #pragma unroll
        for (int i = 0; i < 7; i++) {
            seg0 += (row0 >= LB[i]);
            seg1 += (rend - 1 >= LB[i]);
        }
        split = (seg1 == seg0) ? rend : LB[seg0];
    } else {
        int b2 = b - NB_LW;
        row0 = b2 * TILE_ROWS;
        rend = row0 + TILE_ROWS;
        src = enc4; dst = g_E;
        seg0 = row0 >> 9;   // 512 rows per chunk; tiles aligned -> no split
        seg1 = seg0;
        split = rend;
    }

    float ax = 0.f, ay = 0.f, az = 0.f, aw = 0.f;
    int r = row0;
    #pragma unroll 8
    for (; r < split; ++r) {
        float4 v = __ldg(&src[r * (H_ / 4) + t]);
        ax += v.x; ay += v.y; az += v.z; aw += v.w;
    }
    {
        float* p = dst + seg0 * H_ + t * 4;
        atomicAdd(p + 0, ax); atomicAdd(p + 1, ay);
        atomicAdd(p + 2, az); atomicAdd(p + 3, aw);
    }
    if (r < rend) {
        ax = ay = az = aw = 0.f;
        #pragma unroll 8
        for (; r < rend; ++r) {
            float4 v = __ldg(&src[r * (H_ / 4) + t]);
            ax += v.x; ay += v.y; az += v.z; aw += v.w;
        }
        float* p = dst + seg1 * H_ + t * 4;
        atomicAdd(p + 0, ax); atomicAdd(p + 1, ay);
        atomicAdd(p + 2, az); atomicAdd(p + 3, aw);
    }

    // ---------------- Last-arrival gate ----------------
    __threadfence();
    __shared__ bool is_last;
    if (t == 0)
        is_last = (atomicAdd(&g_count, 1u) == (unsigned)(gridDim.x - 1));
    __syncthreads();
    if (!is_last) return;
    __threadfence();  // acquire accumulators published by other blocks

    // ---------------- Phase 2: finalize (ONE block; compact, L2-fed) -------
    // note_end_chunk_ids: detect int64 vs int32 (values small nonneg, sorted)
    const int* i32 = (const int*)ids_raw;
    int id0, id1, id2, id3;
    if (i32[1] == 0 && i32[3] == 0) {            // int64 layout
        const long long* i64 = (const long long*)ids_raw;
        id0 = (int)i64[0]; id1 = (int)i64[1]; id2 = (int)i64[2]; id3 = (int)i64[3];
    } else {
        id0 = i32[0]; id1 = i32[1]; id2 = i32[2]; id3 = i32[3];
    }

    // w(n,c) into shared (tiny): softmax over notes of the 0/-1e9 mask
    __shared__ float s_wn[NN_][8];
    if (t < 32) {
        int c = t & 7, n = t >> 3;
        int k = (id0 < c) + (id1 < c) + (id2 < c) + (id3 < c);
        int idn = (n == 0) ? id0 : (n == 1) ? id1 : (n == 2) ? id2 : id3;
        s_wn[n][c] = (k == 0) ? 0.25f : ((idn < c) ? (1.0f / (float)k) : 0.0f);
    }
    __syncthreads();

    const int SL[15] = {1113,1114,1115, 2229,2230, 3344,3345, 4459,4460,
                        5574,5575, 6689,6690, 7804,7805};
    const int SC[15] = {0,0,0, 1,1, 2,2, 3,3, 4,4, 5,5, 6,6};
    const int SM[15] = {8,8,1, 8,2, 8,3, 8,4, 8,5, 8,6, 8,7};

    for (int hh = 0; hh < H_ / 192; hh++) {
        const int h = t + hh * 192;

        // Prefix sums of encoding chunk sums (L2-resident reads)
        float Pm[9];
        Pm[0] = 0.0f;
        #pragma unroll
        for (int m = 1; m <= 8; m++) Pm[m] = Pm[m - 1] + g_E[(m - 1) * H_ + h];
        const float Ptot = Pm[8];

        for (int n = 0; n < NN_; n++) {
            float gacc = 0.0f;
            #pragma unroll
            for (int c = 0; c < 8; c++) gacc += s_wn[n][c] * g_G[c * H_ + h];
            float score = Ptot * gacc;
            #pragma unroll
            for (int j = 0; j < 15; j++) {
                float d = s_wn[n][SC[j]] - s_wn[n][SC[j] + 1];
                score += d * __ldg(&lw[SL[j] * H_ + h]) * Pm[SM[j]];
            }
            out[n * H_ + h] = 1.0f / (1.0f + expf(-score));
        }
    }

    // ---------------- Restore state for the next graph replay ----------------
    __syncthreads();
    for (int i = t; i < 8 * H_; i += 192) { g_G[i] = 0.0f; g_E[i] = 0.0f; }
    if (t == 0) g_count = 0;
}

extern "C" void kernel_launch(void* const* d_in, const int* in_sizes, int n_in,
                              void* d_out, int out_size) {
    const float* encoding      = (const float*)d_in[0];
    // d_in[1] = label_queries: provably unused (softmax over notes cancels it)
    const float* label_weights = (const float*)d_in[2];
    const void*  ids           = d_in[3];
    float* out = (float*)d_out;

    fused_kernel<<<NB, 192>>>((const float4*)label_weights,
                              (const float4*)encoding,
                              label_weights, ids, out);
}